// round 10
// baseline (speedup 1.0000x reference)
#include <cuda_runtime.h>
#include <cuda_fp16.h>
#include <stdint.h>
#include <math.h>

#define TOK 2048
#define HID 1024
#define NEXP 8
#define INTER 4096
#define SOFTCAP 30.0f

// ---------------------------------------------------------------------------
// Device-global scratch
// ---------------------------------------------------------------------------
__device__ int    g_cnt[NEXP];
__device__ int    g_list[NEXP][TOK];
__device__ float  g_wl[NEXP][TOK];

__device__ __half g_xh[TOK * HID];
__device__ __half g_w1h[(size_t)NEXP * INTER * HID];
__device__ __half g_w3h[(size_t)NEXP * INTER * HID];
__device__ __half g_w2h[(size_t)NEXP * HID * INTER];
__device__ __half g_acth[(size_t)NEXP * TOK * INTER];

// ---------------------------------------------------------------------------
// PTX helpers (baseline ISA, valid on plain sm_103 target)
// ---------------------------------------------------------------------------
__device__ __forceinline__ uint32_t smem_u32(const void* p) {
    uint32_t a;
    asm("{ .reg .u64 t; cvta.to.shared.u64 t, %1; cvt.u32.u64 %0, t; }"
        : "=r"(a) : "l"(p));
    return a;
}

__device__ __forceinline__ void cpasync16(uint32_t smem, const void* g) {
    asm volatile("cp.async.cg.shared.global [%0], [%1], 16;"
                 :: "r"(smem), "l"(g) : "memory");
}
#define CP_COMMIT() asm volatile("cp.async.commit_group;" ::: "memory")
#define CP_WAIT(n)  asm volatile("cp.async.wait_group %0;" :: "n"(n) : "memory")

__device__ __forceinline__ void ldsm4(uint32_t* r, uint32_t addr) {
    asm volatile("ldmatrix.sync.aligned.m8n8.x4.shared.b16 {%0,%1,%2,%3}, [%4];"
                 : "=r"(r[0]), "=r"(r[1]), "=r"(r[2]), "=r"(r[3]) : "r"(addr));
}

__device__ __forceinline__ void mma16816(float* d, const uint32_t* a,
                                         const uint32_t* b) {
    asm volatile(
        "mma.sync.aligned.m16n8k16.row.col.f32.f16.f16.f32 "
        "{%0,%1,%2,%3}, {%4,%5,%6,%7}, {%8,%9}, {%0,%1,%2,%3};"
        : "+f"(d[0]), "+f"(d[1]), "+f"(d[2]), "+f"(d[3])
        : "r"(a[0]), "r"(a[1]), "r"(a[2]), "r"(a[3]), "r"(b[0]), "r"(b[1]));
}

// ---------------------------------------------------------------------------
// prep: convert x f32->f16 (4 float4/thread), zero out, zero counters
// ---------------------------------------------------------------------------
__global__ void k_prep(const float4* __restrict__ x, __half* __restrict__ xh,
                       float4* __restrict__ out4, int n4) {
    if (blockIdx.x == 0 && threadIdx.x < NEXP) g_cnt[threadIdx.x] = 0;
    int base = blockIdx.x * blockDim.x + threadIdx.x;
    int stride = gridDim.x * blockDim.x;
#pragma unroll
    for (int j = 0; j < 4; j++) {
        int i = base + j * stride;
        if (i < n4) {
            float4 v = x[i];
            __half2 h0 = __floats2half2_rn(v.x, v.y);
            __half2 h1 = __floats2half2_rn(v.z, v.w);
            uint2 u;
            u.x = *(uint32_t*)&h0;
            u.y = *(uint32_t*)&h1;
            *(uint2*)(xh + (size_t)i * 4) = u;
            out4[i] = make_float4(0.f, 0.f, 0.f, 0.f);
        }
    }
}

// ---------------------------------------------------------------------------
// w1 + w3 conversion, 4 float4 per thread (MLP=4)
// ---------------------------------------------------------------------------
__global__ void k_convw(const float4* __restrict__ w1, const float4* __restrict__ w3,
                        __half* __restrict__ w1h, __half* __restrict__ w3h, int n4) {
    int base = blockIdx.x * blockDim.x + threadIdx.x;
    int stride = gridDim.x * blockDim.x;
#pragma unroll
    for (int j = 0; j < 4; j++) {
        int i = base + j * stride;
        const float4* src = w1;
        __half* dst = w1h;
        int ii = i;
        if (ii >= n4) { src = w3; dst = w3h; ii -= n4; }
        float4 v = src[ii];
        __half2 h0 = __floats2half2_rn(v.x, v.y);
        __half2 h1 = __floats2half2_rn(v.z, v.w);
        uint2 u;
        u.x = *(uint32_t*)&h0;
        u.y = *(uint32_t*)&h1;
        *(uint2*)(dst + (size_t)ii * 4) = u;
    }
}

// ---------------------------------------------------------------------------
// Router
// ---------------------------------------------------------------------------
__global__ void k_router(const float* __restrict__ x, const float* __restrict__ wg) {
    const int t = blockIdx.x;
    const float* xr = x + (size_t)t * HID;

    float acc[NEXP];
#pragma unroll
    for (int e = 0; e < NEXP; e++) acc[e] = 0.0f;

    for (int h = threadIdx.x; h < HID; h += 128) {
        float xv = xr[h];
#pragma unroll
        for (int e = 0; e < NEXP; e++)
            acc[e] = fmaf(xv, wg[e * HID + h], acc[e]);
    }
#pragma unroll
    for (int o = 16; o > 0; o >>= 1) {
#pragma unroll
        for (int e = 0; e < NEXP; e++)
            acc[e] += __shfl_down_sync(0xffffffffu, acc[e], o);
    }

    __shared__ float red[4][NEXP];
    int wid = threadIdx.x >> 5;
    int lane = threadIdx.x & 31;
    if (lane == 0) {
#pragma unroll
        for (int e = 0; e < NEXP; e++) red[wid][e] = acc[e];
    }
    __syncthreads();

    if (threadIdx.x == 0) {
        float l[NEXP];
#pragma unroll
        for (int e = 0; e < NEXP; e++) {
            float v = red[0][e] + red[1][e] + red[2][e] + red[3][e];
            l[e] = SOFTCAP * tanhf(v * (1.0f / SOFTCAP));
        }
        int i0 = 0;
#pragma unroll
        for (int e = 1; e < NEXP; e++)
            if (l[e] > l[i0]) i0 = e;
        int i1 = (i0 == 0) ? 1 : 0;
#pragma unroll
        for (int e = 0; e < NEXP; e++)
            if (e != i0 && l[e] > l[i1]) i1 = e;

        float m = l[i0];
        float e0 = expf(l[i0] - m);
        float e1 = expf(l[i1] - m);
        float inv = 1.0f / (e0 + e1);

        int p0 = atomicAdd(&g_cnt[i0], 1);
        g_list[i0][p0] = t;
        g_wl[i0][p0] = e0 * inv;
        int p1 = atomicAdd(&g_cnt[i1], 1);
        g_list[i1][p1] = t;
        g_wl[i1][p1] = e1 * inv;
    }
}

// ---------------------------------------------------------------------------
// Shared GEMM geometry: CTA tile 64(M) x 64(N), K-chunk 128 stored as two
// 64-col halves of 128B swizzled rows; 2-stage; ONE barrier per chunk.
// 8 warps = 2(M) x 4(N), warp tile 32x16.
// Slot mapping (per thread, i = 0..3): lin = tid + 256*i in [0,1024):
//   half = lin>>9, r = (lin&511)>>3, kc = lin&7
//   smem off = half*8192 + r*128 + ((kc*16) ^ ((r&7)*16))
// ---------------------------------------------------------------------------
#define G13_SMEM 99328
#define G2_SMEM  66560
#define MTILES 32
#define CONVX 2
#define KSPLIT 4

__global__ void __launch_bounds__(256, 2) k_g13(const __half* __restrict__ Xh,
                                                const __half* __restrict__ W1,
                                                const __half* __restrict__ W3,
                                                const float* __restrict__ W2f) {
    extern __shared__ char smem[];
    const int tid = threadIdx.x;

    // ---- converter CTAs: stream w2 f32 -> f16 (overlapped with GEMM) ----
    if (blockIdx.x >= MTILES) {
        int cid = ((blockIdx.x - MTILES) * gridDim.y + blockIdx.y) * gridDim.z
                  + blockIdx.z;                        // 0 .. CONVX*64*8-1
        const int nconv = CONVX * (INTER / 64) * NEXP; // 1024
        const size_t n4 = (size_t)NEXP * HID * INTER / 4;
        size_t i = (size_t)cid * 256 + tid;
        const size_t stride = (size_t)nconv * 256;
        for (; i < n4; i += stride) {
            float4 v = ((const float4*)W2f)[i];
            __half2 h0 = __floats2half2_rn(v.x, v.y);
            __half2 h1 = __floats2half2_rn(v.z, v.w);
            uint2 u;
            u.x = *(uint32_t*)&h0;
            u.y = *(uint32_t*)&h1;
            *(uint2*)(g_w2h + i * 4) = u;
        }
        return;
    }

    const uint32_t sb = smem_u32(smem);
    int* rows_s = (int*)smem;

    const int e = blockIdx.z;
    const int cnt = g_cnt[e];
    const int m0 = blockIdx.x * 64;
    if (m0 >= cnt) return;
    const int n0 = blockIdx.y * 64;

    if (tid < 64) {
        int m = m0 + tid;
        rows_s[tid] = g_list[e][m < cnt ? m : cnt - 1];
    }
    __syncthreads();

    const uint32_t sA = sb + 1024;     // 2 x 16384
    const uint32_t sB1 = sb + 33792;   // 2 x 16384
    const uint32_t sB3 = sb + 66560;   // 2 x 16384

    size_t arow[4], brow[4];
    uint32_t soff[4];
#pragma unroll
    for (int i = 0; i < 4; i++) {
        int lin = tid + 256 * i;
        int half = lin >> 9;
        int r = (lin & 511) >> 3;
        int kc = lin & 7;
        soff[i] = (uint32_t)half * 8192u + ((uint32_t)r << 7) +
                  (((uint32_t)kc << 4) ^ (((uint32_t)(r & 7)) << 4));
        arow[i] = (size_t)rows_s[r] * HID + half * 64 + kc * 8;
        brow[i] = ((size_t)e * INTER + n0 + r) * HID + half * 64 + kc * 8;
    }

    const int lane = tid & 31;
    const int w = tid >> 5;
    const int mw = (w >> 2) * 32;   // 0 or 32
    const int nw = (w & 3) * 16;    // 0,16,32,48
    const int mat = lane >> 3;

    float acc1[2][2][4], acc3[2][2][4];
#pragma unroll
    for (int mi = 0; mi < 2; mi++)
#pragma unroll
        for (int nj = 0; nj < 2; nj++)
#pragma unroll
            for (int q = 0; q < 4; q++) { acc1[mi][nj][q] = 0.0f; acc3[mi][nj][q] = 0.0f; }

#define G13_ISSUE(c, buf)                                                      \
    do {                                                                       \
        const uint32_t o = (uint32_t)(buf) * 16384u;                           \
        const int k0 = (c) << 7;                                               \
        _Pragma("unroll")                                                      \
        for (int i = 0; i < 4; i++) {                                          \
            cpasync16(sA + o + soff[i], Xh + arow[i] + k0);                    \
            cpasync16(sB1 + o + soff[i], W1 + brow[i] + k0);                   \
            cpasync16(sB3 + o + soff[i], W3 + brow[i] + k0);                   \
        }                                                                      \
        CP_COMMIT();                                                           \
    } while (0)

    G13_ISSUE(0, 0);

    const int nch = HID / 128;  // 8
    for (int it = 0; it < nch; it++) {
        CP_WAIT(0);
        __syncthreads();   // chunk `it` visible; all warps done MMA(it-1)
        if (it + 1 < nch)
            G13_ISSUE(it + 1, (it + 1) & 1);   // lands during MMA(it)

        const uint32_t o = (uint32_t)(it & 1) * 16384u;
        const uint32_t aB = sA + o;
        const uint32_t b1B = sB1 + o;
        const uint32_t b3B = sB3 + o;

#pragma unroll
        for (int kk = 0; kk < 8; kk++) {
            const uint32_t hoff = (uint32_t)(kk >> 2) * 8192u;
            const int kk2 = kk & 3;
            uint32_t af[2][4];
#pragma unroll
            for (int mi = 0; mi < 2; mi++) {
                int row = mw + mi * 16 + (lane & 7) + (mat & 1) * 8;
                int kb = kk2 * 32 + (mat >> 1) * 16;
                uint32_t so = hoff + ((uint32_t)row << 7) +
                              ((uint32_t)kb ^ (((uint32_t)(row & 7)) << 4));
                ldsm4(af[mi], aB + so);
            }
            int brw = nw + (mat >> 1) * 8 + (lane & 7);
            int bkb = kk2 * 32 + (mat & 1) * 16;
            uint32_t bso = hoff + ((uint32_t)brw << 7) +
                           ((uint32_t)bkb ^ (((uint32_t)(brw & 7)) << 4));
            uint32_t bf1[4], bf3[4];
            ldsm4(bf1, b1B + bso);
            ldsm4(bf3, b3B + bso);
#pragma unroll
            for (int mi = 0; mi < 2; mi++) {
                mma16816(acc1[mi][0], af[mi], bf1 + 0);
                mma16816(acc1[mi][1], af[mi], bf1 + 2);
                mma16816(acc3[mi][0], af[mi], bf3 + 0);
                mma16816(acc3[mi][1], af[mi], bf3 + 2);
            }
        }
    }

    // epilogue: act = gelu(h1) * h3 -> fp16, compact rows
#pragma unroll
    for (int mi = 0; mi < 2; mi++) {
        int m1 = m0 + mw + mi * 16 + (lane >> 2);
#pragma unroll
        for (int nj = 0; nj < 2; nj++) {
            int n = n0 + nw + nj * 8 + (lane & 3) * 2;
            __half* op = g_acth + ((size_t)e * TOK + m1) * INTER + n;
            if (m1 < cnt) {
                float a0 = acc1[mi][nj][0], a1 = acc1[mi][nj][1];
                float v0 = 0.5f * a0 * (1.0f + erff(a0 * 0.70710678118654752f)) * acc3[mi][nj][0];
                float v1 = 0.5f * a1 * (1.0f + erff(a1 * 0.70710678118654752f)) * acc3[mi][nj][1];
                *(__half2*)op = __floats2half2_rn(v0, v1);
            }
            if (m1 + 8 < cnt) {
                float a2 = acc1[mi][nj][2], a3 = acc1[mi][nj][3];
                float v2 = 0.5f * a2 * (1.0f + erff(a2 * 0.70710678118654752f)) * acc3[mi][nj][2];
                float v3 = 0.5f * a3 * (1.0f + erff(a3 * 0.70710678118654752f)) * acc3[mi][nj][3];
                *(__half2*)(op + (size_t)8 * INTER) = __floats2half2_rn(v2, v3);
            }
        }
    }
}

// ---------------------------------------------------------------------------
// GEMM2: out[token] += w * (act @ w2^T), f32 atomics.
// CTA 64x64, K-SPLIT=4 (K range 1024 = 8 chunks of 128), 2-stage, 1 barrier.
// grid: x = m-tiles (32), y = n-tile(16) | ksplit(4) -> 64, z = expert.
// ---------------------------------------------------------------------------
__global__ void __launch_bounds__(256, 2) k_g2(const __half* __restrict__ W2,
                                               float* __restrict__ out) {
    extern __shared__ char smem[];
    const uint32_t sb = smem_u32(smem);
    int* tok_s = (int*)smem;             // [64]
    float* wt_s = (float*)(smem + 256);  // [64]

    const int e = blockIdx.z;
    const int cnt = g_cnt[e];
    const int m0 = blockIdx.x * 64;
    if (m0 >= cnt) return;
    const int n0 = (blockIdx.y & 15) * 64;
    const int kbase = (blockIdx.y >> 4) * (INTER / KSPLIT);  // 0,1024,2048,3072

    const int tid = threadIdx.x;
    if (tid < 64) {
        int m = m0 + tid;
        int mi2 = m < cnt ? m : cnt - 1;
        tok_s[tid] = g_list[e][mi2];
        wt_s[tid] = g_wl[e][mi2];
    }
    __syncthreads();

    const uint32_t sA = sb + 1024;    // 2 x 16384
    const uint32_t sB = sb + 33792;   // 2 x 16384

    size_t arow[4], brow[4];
    uint32_t soff[4];
#pragma unroll
    for (int i = 0; i < 4; i++) {
        int lin = tid + 256 * i;
        int half = lin >> 9;
        int r = (lin & 511) >> 3;
        int kc = lin & 7;
        soff[i] = (uint32_t)half * 8192u + ((uint32_t)r << 7) +
                  (((uint32_t)kc << 4) ^ (((uint32_t)(r & 7)) << 4));
        arow[i] = ((size_t)e * TOK + m0 + r) * INTER + kbase + half * 64 + kc * 8;
        brow[i] = ((size_t)e * HID + n0 + r) * INTER + kbase + half * 64 + kc * 8;
    }

    const int lane = tid & 31;
    const int w = tid >> 5;
    const int mw = (w >> 2) * 32;
    const int nw = (w & 3) * 16;
    const int mat = lane >> 3;

    float acc[2][2][4];
#pragma unroll
    for (int mi = 0; mi < 2; mi++)
#pragma unroll
        for (int nj = 0; nj < 2; nj++)
#pragma unroll
            for (int q = 0; q < 4; q++) acc[mi][nj][q] = 0.0f;

#define G2_ISSUE(c, buf)                                                       \
    do {                                                                       \
        const uint32_t o = (uint32_t)(buf) * 16384u;                           \
        const int k0 = (c) << 7;                                               \
        _Pragma("unroll")                                                      \
        for (int i = 0; i < 4; i++) {                                          \
            cpasync16(sA + o + soff[i], g_acth + arow[i] + k0);                \
            cpasync16(sB + o + soff[i], W2 + brow[i] + k0);                    \
        }                                                                      \
        CP_COMMIT();                                                           \
    } while (0)

    G2_ISSUE(0, 0);

    const int nch = (INTER / KSPLIT) / 128;  // 8
    for (int it = 0; it < nch; it++) {
        CP_WAIT(0);
        __syncthreads();
        if (it + 1 < nch)
            G2_ISSUE(it + 1, (it + 1) & 1);

        const uint32_t o = (uint32_t)(it & 1) * 16384u;
        const uint32_t aB = sA + o;
        const uint32_t bB = sB + o;

#pragma unroll
        for (int kk = 0; kk < 8; kk++) {
            const uint32_t hoff = (uint32_t)(kk >> 2) * 8192u;
            const int kk2 = kk & 3;
            uint32_t af[2][4];
#pragma unroll
            for (int mi = 0; mi < 2; mi++) {
                int row = mw + mi * 16 + (lane & 7) + (mat & 1) * 8;
                int kb = kk2 * 32 + (mat >> 1) * 16;
                uint32_t so = hoff + ((uint32_t)row << 7) +
                              ((uint32_t)kb ^ (((uint32_t)(row & 7)) << 4));
                ldsm4(af[mi], aB + so);
            }
            int brw = nw + (mat >> 1) * 8 + (lane & 7);
            int bkb = kk2 * 32 + (mat & 1) * 16;
            uint32_t bso = hoff + ((uint32_t)brw << 7) +
                           ((uint32_t)bkb ^ (((uint32_t)(brw & 7)) << 4));
            uint32_t bf[4];
            ldsm4(bf, bB + bso);
#pragma unroll
            for (int mi = 0; mi < 2; mi++) {
                mma16816(acc[mi][0], af[mi], bf + 0);
                mma16816(acc[mi][1], af[mi], bf + 2);
            }
        }
    }

    // epilogue: weighted atomic scatter-add into out
#pragma unroll
    for (int mi = 0; mi < 2; mi++) {
        int mm = mw + mi * 16 + (lane >> 2);
        int m1 = m0 + mm;
#pragma unroll
        for (int nj = 0; nj < 2; nj++) {
            int n = n0 + nw + nj * 8 + (lane & 3) * 2;
            if (m1 < cnt) {
                int t = tok_s[mm];
                float ww = wt_s[mm];
                float* op = out + (size_t)t * HID + n;
                atomicAdd(op + 0, ww * acc[mi][nj][0]);
                atomicAdd(op + 1, ww * acc[mi][nj][1]);
            }
            if (m1 + 8 < cnt) {
                int t = tok_s[mm + 8];
                float ww = wt_s[mm + 8];
                float* op = out + (size_t)t * HID + n;
                atomicAdd(op + 0, ww * acc[mi][nj][2]);
                atomicAdd(op + 1, ww * acc[mi][nj][3]);
            }
        }
    }
}

// ---------------------------------------------------------------------------
// launch
// ---------------------------------------------------------------------------
extern "C" void kernel_launch(void* const* d_in, const int* in_sizes, int n_in,
                              void* d_out, int out_size) {
    const float* x  = (const float*)d_in[0];
    const float* wg = (const float*)d_in[1];
    const float* w1 = (const float*)d_in[2];
    const float* w3 = (const float*)d_in[3];
    const float* w2 = (const float*)d_in[4];
    float* out = (float*)d_out;

    cudaFuncSetAttribute(k_g13, cudaFuncAttributeMaxDynamicSharedMemorySize, G13_SMEM);
    cudaFuncSetAttribute(k_g2, cudaFuncAttributeMaxDynamicSharedMemorySize, G2_SMEM);

    __half *xh, *w1h, *w3h, *w2h;
    cudaGetSymbolAddress((void**)&xh, g_xh);
    cudaGetSymbolAddress((void**)&w1h, g_w1h);
    cudaGetSymbolAddress((void**)&w3h, g_w3h);
    cudaGetSymbolAddress((void**)&w2h, g_w2h);

    const int n4 = TOK * HID / 4;
    const int nw4 = (int)((size_t)NEXP * INTER * HID / 4);
    k_prep<<<(n4 / 4 + 255) / 256, 256>>>((const float4*)x, xh, (float4*)out, n4);
    k_router<<<TOK, 128>>>(x, wg);
    k_convw<<<(2 * nw4 / 4) / 256, 256>>>((const float4*)w1, (const float4*)w3, w1h, w3h, nw4);

    // x-dim: [0,32) GEMM m-tiles, [32,34) w2 converter CTAs (overlapped)
    k_g13<<<dim3(MTILES + CONVX, INTER / 64, NEXP), 256, G13_SMEM>>>(xh, w1h, w3h, w2);
    k_g2<<<dim3(TOK / 64, 16 * KSPLIT, NEXP), 256, G2_SMEM>>>(w2h, out);
}

// round 13
// speedup vs baseline: 1.0803x; 1.0803x over previous
#include <cuda_runtime.h>
#include <cuda_fp16.h>
#include <stdint.h>
#include <math.h>

#define TOK 2048
#define HID 1024
#define NEXP 8
#define INTER 4096
#define SOFTCAP 30.0f

// ---------------------------------------------------------------------------
// Device-global scratch
// ---------------------------------------------------------------------------
__device__ int    g_cnt[NEXP];
__device__ int    g_list[NEXP][TOK];
__device__ float  g_wl[NEXP][TOK];

__device__ __half g_xh[TOK * HID];
__device__ __half g_w1h[(size_t)NEXP * INTER * HID];
__device__ __half g_w3h[(size_t)NEXP * INTER * HID];
__device__ __half g_w2h[(size_t)NEXP * HID * INTER];
__device__ __half g_h1h[(size_t)NEXP * TOK * INTER];
__device__ __half g_acth[(size_t)NEXP * TOK * INTER];

// ---------------------------------------------------------------------------
// PTX helpers (baseline ISA, valid on plain sm_103 target)
// ---------------------------------------------------------------------------
__device__ __forceinline__ uint32_t smem_u32(const void* p) {
    uint32_t a;
    asm("{ .reg .u64 t; cvta.to.shared.u64 t, %1; cvt.u32.u64 %0, t; }"
        : "=r"(a) : "l"(p));
    return a;
}

__device__ __forceinline__ void cpasync16(uint32_t smem, const void* g) {
    asm volatile("cp.async.cg.shared.global [%0], [%1], 16;"
                 :: "r"(smem), "l"(g) : "memory");
}
#define CP_COMMIT() asm volatile("cp.async.commit_group;" ::: "memory")
#define CP_WAIT(n)  asm volatile("cp.async.wait_group %0;" :: "n"(n) : "memory")

__device__ __forceinline__ void ldsm4(uint32_t* r, uint32_t addr) {
    asm volatile("ldmatrix.sync.aligned.m8n8.x4.shared.b16 {%0,%1,%2,%3}, [%4];"
                 : "=r"(r[0]), "=r"(r[1]), "=r"(r[2]), "=r"(r[3]) : "r"(addr));
}

__device__ __forceinline__ void mma16816(float* d, const uint32_t* a,
                                         const uint32_t* b) {
    asm volatile(
        "mma.sync.aligned.m16n8k16.row.col.f32.f16.f16.f32 "
        "{%0,%1,%2,%3}, {%4,%5,%6,%7}, {%8,%9}, {%0,%1,%2,%3};"
        : "+f"(d[0]), "+f"(d[1]), "+f"(d[2]), "+f"(d[3])
        : "r"(a[0]), "r"(a[1]), "r"(a[2]), "r"(a[3]), "r"(b[0]), "r"(b[1]));
}

// grid-stride f32 -> f16 converter body
__device__ __forceinline__ void conv_stream(const float4* __restrict__ src,
                                            __half* __restrict__ dst,
                                            size_t n4, size_t start, size_t stride) {
    for (size_t i = start; i < n4; i += stride) {
        float4 v = src[i];
        __half2 h0 = __floats2half2_rn(v.x, v.y);
        __half2 h1 = __floats2half2_rn(v.z, v.w);
        uint2 u;
        u.x = *(uint32_t*)&h0;
        u.y = *(uint32_t*)&h1;
        *(uint2*)(dst + i * 4) = u;
    }
}

// ---------------------------------------------------------------------------
// prep: convert x f32->f16, zero out, zero counters
// ---------------------------------------------------------------------------
__global__ void k_prep(const float4* __restrict__ x, __half* __restrict__ xh,
                       float4* __restrict__ out4, int n4) {
    if (blockIdx.x == 0 && threadIdx.x < NEXP) g_cnt[threadIdx.x] = 0;
    int base = blockIdx.x * blockDim.x + threadIdx.x;
    int stride = gridDim.x * blockDim.x;
#pragma unroll
    for (int j = 0; j < 4; j++) {
        int i = base + j * stride;
        if (i < n4) {
            float4 v = x[i];
            __half2 h0 = __floats2half2_rn(v.x, v.y);
            __half2 h1 = __floats2half2_rn(v.z, v.w);
            uint2 u;
            u.x = *(uint32_t*)&h0;
            u.y = *(uint32_t*)&h1;
            *(uint2*)(xh + (size_t)i * 4) = u;
            out4[i] = make_float4(0.f, 0.f, 0.f, 0.f);
        }
    }
}

// w1 conversion (the only exposed weight conversion)
__global__ void k_convw(const float4* __restrict__ src, __half* __restrict__ dst,
                        int n4) {
    size_t start = (size_t)blockIdx.x * blockDim.x + threadIdx.x;
    conv_stream(src, dst, (size_t)n4, start, (size_t)gridDim.x * blockDim.x);
}

// ---------------------------------------------------------------------------
// Router
// ---------------------------------------------------------------------------
__global__ void k_router(const float* __restrict__ x, const float* __restrict__ wg) {
    const int t = blockIdx.x;
    const float* xr = x + (size_t)t * HID;

    float acc[NEXP];
#pragma unroll
    for (int e = 0; e < NEXP; e++) acc[e] = 0.0f;

    for (int h = threadIdx.x; h < HID; h += 128) {
        float xv = xr[h];
#pragma unroll
        for (int e = 0; e < NEXP; e++)
            acc[e] = fmaf(xv, wg[e * HID + h], acc[e]);
    }
#pragma unroll
    for (int o = 16; o > 0; o >>= 1) {
#pragma unroll
        for (int e = 0; e < NEXP; e++)
            acc[e] += __shfl_down_sync(0xffffffffu, acc[e], o);
    }

    __shared__ float red[4][NEXP];
    int wid = threadIdx.x >> 5;
    int lane = threadIdx.x & 31;
    if (lane == 0) {
#pragma unroll
        for (int e = 0; e < NEXP; e++) red[wid][e] = acc[e];
    }
    __syncthreads();

    if (threadIdx.x == 0) {
        float l[NEXP];
#pragma unroll
        for (int e = 0; e < NEXP; e++) {
            float v = red[0][e] + red[1][e] + red[2][e] + red[3][e];
            l[e] = SOFTCAP * tanhf(v * (1.0f / SOFTCAP));
        }
        int i0 = 0;
#pragma unroll
        for (int e = 1; e < NEXP; e++)
            if (l[e] > l[i0]) i0 = e;
        int i1 = (i0 == 0) ? 1 : 0;
#pragma unroll
        for (int e = 0; e < NEXP; e++)
            if (e != i0 && l[e] > l[i1]) i1 = e;

        float m = l[i0];
        float e0 = expf(l[i0] - m);
        float e1 = expf(l[i1] - m);
        float inv = 1.0f / (e0 + e1);

        int p0 = atomicAdd(&g_cnt[i0], 1);
        g_list[i0][p0] = t;
        g_wl[i0][p0] = e0 * inv;
        int p1 = atomicAdd(&g_cnt[i1], 1);
        g_list[i1][p1] = t;
        g_wl[i1][p1] = e1 * inv;
    }
}

// ===========================================================================
// GEMM geometry (all three GEMMs): CTA tile 128(M) x 128(N), K-chunk 64,
// 2-stage cp.async, ONE barrier per chunk, 256 threads, 8 warps (2m x 4n),
// warp tile 64x32. smem: hdr 1024 | A 2x16K | B 2x16K = 66560.
// ===========================================================================
#define GM_SMEM 66560
#define MTILES 16
#define CONVX 2

// fragment load + 16 MMA for one kk step
#define FRAG_MMA(aB, bB, accv)                                                  \
    do {                                                                        \
        uint32_t af[4][4];                                                      \
        _Pragma("unroll")                                                       \
        for (int mi = 0; mi < 4; mi++) {                                        \
            int row = mw + mi * 16 + (lane & 7) + (mat & 1) * 8;                \
            int kb = kk * 32 + (mat >> 1) * 16;                                 \
            uint32_t so = ((uint32_t)row << 7) |                                \
                          ((uint32_t)kb ^ (((uint32_t)(row & 7)) << 4));        \
            ldsm4(af[mi], (aB) + so);                                           \
        }                                                                       \
        uint32_t bf[4][2];                                                      \
        _Pragma("unroll")                                                       \
        for (int nb = 0; nb < 2; nb++) {                                        \
            int row = nw + nb * 16 + (mat >> 1) * 8 + (lane & 7);               \
            int kb = kk * 32 + (mat & 1) * 16;                                  \
            uint32_t so = ((uint32_t)row << 7) |                                \
                          ((uint32_t)kb ^ (((uint32_t)(row & 7)) << 4));        \
            uint32_t r4[4];                                                     \
            ldsm4(r4, (bB) + so);                                               \
            bf[nb * 2 + 0][0] = r4[0];                                          \
            bf[nb * 2 + 0][1] = r4[1];                                          \
            bf[nb * 2 + 1][0] = r4[2];                                          \
            bf[nb * 2 + 1][1] = r4[3];                                          \
        }                                                                       \
        _Pragma("unroll")                                                       \
        for (int mi = 0; mi < 4; mi++)                                          \
            _Pragma("unroll")                                                   \
            for (int nj = 0; nj < 4; nj++)                                      \
                mma16816(accv[mi][nj], af[mi], bf[nj]);                         \
    } while (0)

// ---------------------------------------------------------------------------
// g1: h1 = X @ w1^T -> f16 (gathered rows). Converter slots: w3 f32->f16.
// ---------------------------------------------------------------------------
__global__ void __launch_bounds__(256, 2) k_g1(const __half* __restrict__ Xh,
                                               const __half* __restrict__ W1,
                                               const float* __restrict__ W3f) {
    extern __shared__ char smem[];
    const int tid = threadIdx.x;

    if (blockIdx.x >= MTILES) {  // converter CTAs: w3
        int cid = ((blockIdx.x - MTILES) * gridDim.y + blockIdx.y) * gridDim.z
                  + blockIdx.z;
        const int nconv = CONVX * (INTER / 128) * NEXP;  // 512
        const size_t n4 = (size_t)NEXP * INTER * HID / 4;
        conv_stream((const float4*)W3f, g_w3h, n4,
                    (size_t)cid * 256 + tid, (size_t)nconv * 256);
        return;
    }

    const uint32_t sb = smem_u32(smem);
    int* rows_s = (int*)smem;

    const int e = blockIdx.z;
    const int cnt = g_cnt[e];
    const int m0 = blockIdx.x * 128;
    if (m0 >= cnt) return;
    const int n0 = blockIdx.y * 128;

    if (tid < 128) {
        int m = m0 + tid;
        rows_s[tid] = g_list[e][m < cnt ? m : cnt - 1];
    }
    __syncthreads();

    const uint32_t sA = sb + 1024;     // 2 x 16384
    const uint32_t sB = sb + 33792;    // 2 x 16384

    size_t arow[4], brow[4];
    uint32_t soff[4];
#pragma unroll
    for (int i = 0; i < 4; i++) {
        int lin = tid + 256 * i;
        int r = lin >> 3;
        int kc = lin & 7;
        soff[i] = ((uint32_t)r << 7) | (((uint32_t)kc << 4) ^ (((uint32_t)(r & 7)) << 4));
        arow[i] = (size_t)rows_s[r] * HID + kc * 8;
        brow[i] = ((size_t)e * INTER + n0 + r) * HID + kc * 8;
    }

    const int lane = tid & 31;
    const int w = tid >> 5;
    const int mw = (w >> 2) * 64;
    const int nw = (w & 3) * 32;
    const int mat = lane >> 3;

    float acc[4][4][4];
#pragma unroll
    for (int mi = 0; mi < 4; mi++)
#pragma unroll
        for (int nj = 0; nj < 4; nj++)
#pragma unroll
            for (int q = 0; q < 4; q++) acc[mi][nj][q] = 0.0f;

#define G1_ISSUE(c, buf)                                                       \
    do {                                                                       \
        const uint32_t o = (uint32_t)(buf) * 16384u;                           \
        const int k0 = (c) << 6;                                               \
        _Pragma("unroll")                                                      \
        for (int i = 0; i < 4; i++) {                                          \
            cpasync16(sA + o + soff[i], Xh + arow[i] + k0);                    \
            cpasync16(sB + o + soff[i], W1 + brow[i] + k0);                    \
        }                                                                      \
        CP_COMMIT();                                                           \
    } while (0)

    G1_ISSUE(0, 0);
    const int nch = HID / 64;  // 16
    for (int it = 0; it < nch; it++) {
        CP_WAIT(0);
        __syncthreads();
        if (it + 1 < nch) G1_ISSUE(it + 1, (it + 1) & 1);
        const uint32_t o = (uint32_t)(it & 1) * 16384u;
        const uint32_t aB = sA + o;
        const uint32_t bB = sB + o;
#pragma unroll
        for (int kk = 0; kk < 4; kk++) FRAG_MMA(aB, bB, acc);
    }

    // epilogue: h1 -> f16
#pragma unroll
    for (int mi = 0; mi < 4; mi++) {
        int m1 = m0 + mw + mi * 16 + (lane >> 2);
#pragma unroll
        for (int nj = 0; nj < 4; nj++) {
            int n = n0 + nw + nj * 8 + (lane & 3) * 2;
            __half* op = g_h1h + ((size_t)e * TOK + m1) * INTER + n;
            if (m1 < cnt)
                *(__half2*)op = __floats2half2_rn(acc[mi][nj][0], acc[mi][nj][1]);
            if (m1 + 8 < cnt)
                *(__half2*)(op + (size_t)8 * INTER) =
                    __floats2half2_rn(acc[mi][nj][2], acc[mi][nj][3]);
        }
    }
}

// ---------------------------------------------------------------------------
// g3: h3 = X @ w3^T ; act = gelu(h1)*h3 -> f16. Converter slots: w2.
// ---------------------------------------------------------------------------
__global__ void __launch_bounds__(256, 2) k_g3(const __half* __restrict__ Xh,
                                               const __half* __restrict__ W3,
                                               const float* __restrict__ W2f) {
    extern __shared__ char smem[];
    const int tid = threadIdx.x;

    if (blockIdx.x >= MTILES) {  // converter CTAs: w2
        int cid = ((blockIdx.x - MTILES) * gridDim.y + blockIdx.y) * gridDim.z
                  + blockIdx.z;
        const int nconv = CONVX * (INTER / 128) * NEXP;
        const size_t n4 = (size_t)NEXP * HID * INTER / 4;
        conv_stream((const float4*)W2f, g_w2h, n4,
                    (size_t)cid * 256 + tid, (size_t)nconv * 256);
        return;
    }

    const uint32_t sb = smem_u32(smem);
    int* rows_s = (int*)smem;

    const int e = blockIdx.z;
    const int cnt = g_cnt[e];
    const int m0 = blockIdx.x * 128;
    if (m0 >= cnt) return;
    const int n0 = blockIdx.y * 128;

    if (tid < 128) {
        int m = m0 + tid;
        rows_s[tid] = g_list[e][m < cnt ? m : cnt - 1];
    }
    __syncthreads();

    const uint32_t sA = sb + 1024;
    const uint32_t sB = sb + 33792;

    size_t arow[4], brow[4];
    uint32_t soff[4];
#pragma unroll
    for (int i = 0; i < 4; i++) {
        int lin = tid + 256 * i;
        int r = lin >> 3;
        int kc = lin & 7;
        soff[i] = ((uint32_t)r << 7) | (((uint32_t)kc << 4) ^ (((uint32_t)(r & 7)) << 4));
        arow[i] = (size_t)rows_s[r] * HID + kc * 8;
        brow[i] = ((size_t)e * INTER + n0 + r) * HID + kc * 8;
    }

    const int lane = tid & 31;
    const int w = tid >> 5;
    const int mw = (w >> 2) * 64;
    const int nw = (w & 3) * 32;
    const int mat = lane >> 3;

    float acc[4][4][4];
#pragma unroll
    for (int mi = 0; mi < 4; mi++)
#pragma unroll
        for (int nj = 0; nj < 4; nj++)
#pragma unroll
            for (int q = 0; q < 4; q++) acc[mi][nj][q] = 0.0f;

#define G3_ISSUE(c, buf)                                                       \
    do {                                                                       \
        const uint32_t o = (uint32_t)(buf) * 16384u;                           \
        const int k0 = (c) << 6;                                               \
        _Pragma("unroll")                                                      \
        for (int i = 0; i < 4; i++) {                                          \
            cpasync16(sA + o + soff[i], Xh + arow[i] + k0);                    \
            cpasync16(sB + o + soff[i], W3 + brow[i] + k0);                    \
        }                                                                      \
        CP_COMMIT();                                                           \
    } while (0)

    G3_ISSUE(0, 0);
    const int nch = HID / 64;  // 16
    for (int it = 0; it < nch; it++) {
        CP_WAIT(0);
        __syncthreads();
        if (it + 1 < nch) G3_ISSUE(it + 1, (it + 1) & 1);
        const uint32_t o = (uint32_t)(it & 1) * 16384u;
        const uint32_t aB = sA + o;
        const uint32_t bB = sB + o;
#pragma unroll
        for (int kk = 0; kk < 4; kk++) FRAG_MMA(aB, bB, acc);
    }

    // epilogue: act = gelu(h1) * h3 -> f16 (h1 read from L2-hot gmem)
#pragma unroll
    for (int mi = 0; mi < 4; mi++) {
        int m1 = m0 + mw + mi * 16 + (lane >> 2);
#pragma unroll
        for (int nj = 0; nj < 4; nj++) {
            int n = n0 + nw + nj * 8 + (lane & 3) * 2;
            size_t base = ((size_t)e * TOK + m1) * INTER + n;
            if (m1 < cnt) {
                __half2 h1v = *(const __half2*)(g_h1h + base);
                float a0 = __low2float(h1v), a1 = __high2float(h1v);
                float v0 = 0.5f * a0 * (1.0f + erff(a0 * 0.70710678118654752f)) * acc[mi][nj][0];
                float v1 = 0.5f * a1 * (1.0f + erff(a1 * 0.70710678118654752f)) * acc[mi][nj][1];
                *(__half2*)(g_acth + base) = __floats2half2_rn(v0, v1);
            }
            if (m1 + 8 < cnt) {
                __half2 h1v = *(const __half2*)(g_h1h + base + (size_t)8 * INTER);
                float a2 = __low2float(h1v), a3 = __high2float(h1v);
                float v2 = 0.5f * a2 * (1.0f + erff(a2 * 0.70710678118654752f)) * acc[mi][nj][2];
                float v3 = 0.5f * a3 * (1.0f + erff(a3 * 0.70710678118654752f)) * acc[mi][nj][3];
                *(__half2*)(g_acth + base + (size_t)8 * INTER) = __floats2half2_rn(v2, v3);
            }
        }
    }
}

// ---------------------------------------------------------------------------
// g2: out[token] += w * (act @ w2^T), f32 atomics. 128x128, KSPLIT=4.
// grid: x = m-tiles(16), y = n-tile(8) | ksplit(4) -> 32, z = expert.
// ---------------------------------------------------------------------------
#define KSPLIT 4

__global__ void __launch_bounds__(256, 2) k_g2(const __half* __restrict__ W2,
                                               float* __restrict__ out) {
    extern __shared__ char smem[];
    const uint32_t sb = smem_u32(smem);
    int* tok_s = (int*)smem;             // [128]
    float* wt_s = (float*)(smem + 512);  // [128]

    const int e = blockIdx.z;
    const int cnt = g_cnt[e];
    const int m0 = blockIdx.x * 128;
    if (m0 >= cnt) return;
    const int n0 = (blockIdx.y & 7) * 128;
    const int kbase = (blockIdx.y >> 3) * (INTER / KSPLIT);

    const int tid = threadIdx.x;
    if (tid < 128) {
        int m = m0 + tid;
        int mi2 = m < cnt ? m : cnt - 1;
        tok_s[tid] = g_list[e][mi2];
        wt_s[tid] = g_wl[e][mi2];
    }
    __syncthreads();

    const uint32_t sA = sb + 1024;
    const uint32_t sB = sb + 33792;

    size_t arow[4], brow[4];
    uint32_t soff[4];
#pragma unroll
    for (int i = 0; i < 4; i++) {
        int lin = tid + 256 * i;
        int r = lin >> 3;
        int kc = lin & 7;
        soff[i] = ((uint32_t)r << 7) | (((uint32_t)kc << 4) ^ (((uint32_t)(r & 7)) << 4));
        arow[i] = ((size_t)e * TOK + m0 + r) * INTER + kbase + kc * 8;
        brow[i] = ((size_t)e * HID + n0 + r) * INTER + kbase + kc * 8;
    }

    const int lane = tid & 31;
    const int w = tid >> 5;
    const int mw = (w >> 2) * 64;
    const int nw = (w & 3) * 32;
    const int mat = lane >> 3;

    float acc[4][4][4];
#pragma unroll
    for (int mi = 0; mi < 4; mi++)
#pragma unroll
        for (int nj = 0; nj < 4; nj++)
#pragma unroll
            for (int q = 0; q < 4; q++) acc[mi][nj][q] = 0.0f;

#define G2_ISSUE(c, buf)                                                       \
    do {                                                                       \
        const uint32_t o = (uint32_t)(buf) * 16384u;                           \
        const int k0 = (c) << 6;                                               \
        _Pragma("unroll")                                                      \
        for (int i = 0; i < 4; i++) {                                          \
            cpasync16(sA + o + soff[i], g_acth + arow[i] + k0);                \
            cpasync16(sB + o + soff[i], W2 + brow[i] + k0);                    \
        }                                                                      \
        CP_COMMIT();                                                           \
    } while (0)

    G2_ISSUE(0, 0);
    const int nch = (INTER / KSPLIT) / 64;  // 16
    for (int it = 0; it < nch; it++) {
        CP_WAIT(0);
        __syncthreads();
        if (it + 1 < nch) G2_ISSUE(it + 1, (it + 1) & 1);
        const uint32_t o = (uint32_t)(it & 1) * 16384u;
        const uint32_t aB = sA + o;
        const uint32_t bB = sB + o;
#pragma unroll
        for (int kk = 0; kk < 4; kk++) FRAG_MMA(aB, bB, acc);
    }

    // epilogue: weighted atomic scatter-add into out
#pragma unroll
    for (int mi = 0; mi < 4; mi++) {
        int mm = mw + mi * 16 + (lane >> 2);
        int m1 = m0 + mm;
#pragma unroll
        for (int nj = 0; nj < 4; nj++) {
            int n = n0 + nw + nj * 8 + (lane & 3) * 2;
            if (m1 < cnt) {
                int t = tok_s[mm];
                float ww = wt_s[mm];
                float* op = out + (size_t)t * HID + n;
                atomicAdd(op + 0, ww * acc[mi][nj][0]);
                atomicAdd(op + 1, ww * acc[mi][nj][1]);
            }
            if (m1 + 8 < cnt) {
                int t = tok_s[mm + 8];
                float ww = wt_s[mm + 8];
                float* op = out + (size_t)t * HID + n;
                atomicAdd(op + 0, ww * acc[mi][nj][2]);
                atomicAdd(op + 1, ww * acc[mi][nj][3]);
            }
        }
    }
}

// ---------------------------------------------------------------------------
// launch
// ---------------------------------------------------------------------------
extern "C" void kernel_launch(void* const* d_in, const int* in_sizes, int n_in,
                              void* d_out, int out_size) {
    const float* x  = (const float*)d_in[0];
    const float* wg = (const float*)d_in[1];
    const float* w1 = (const float*)d_in[2];
    const float* w3 = (const float*)d_in[3];
    const float* w2 = (const float*)d_in[4];
    float* out = (float*)d_out;

    cudaFuncSetAttribute(k_g1, cudaFuncAttributeMaxDynamicSharedMemorySize, GM_SMEM);
    cudaFuncSetAttribute(k_g3, cudaFuncAttributeMaxDynamicSharedMemorySize, GM_SMEM);
    cudaFuncSetAttribute(k_g2, cudaFuncAttributeMaxDynamicSharedMemorySize, GM_SMEM);

    __half *xh, *w1h, *w3h, *w2h;
    cudaGetSymbolAddress((void**)&xh, g_xh);
    cudaGetSymbolAddress((void**)&w1h, g_w1h);
    cudaGetSymbolAddress((void**)&w3h, g_w3h);
    cudaGetSymbolAddress((void**)&w2h, g_w2h);

    const int n4 = TOK * HID / 4;
    const int nw4 = (int)((size_t)NEXP * INTER * HID / 4);

    k_prep<<<(n4 / 4 + 255) / 256, 256>>>((const float4*)x, xh, (float4*)out, n4);
    k_router<<<TOK, 128>>>(x, wg);
    k_convw<<<(nw4 / 4) / 256, 256>>>((const float4*)w1, w1h, nw4);

    // g1: GEMM m-tiles [0,16) + w3 converter slots [16,18)
    k_g1<<<dim3(MTILES + CONVX, INTER / 128, NEXP), 256, GM_SMEM>>>(xh, w1h, w3);
    // g3: GEMM + w2 converter slots
    k_g3<<<dim3(MTILES + CONVX, INTER / 128, NEXP), 256, GM_SMEM>>>(xh, w3h, w2);
    k_g2<<<dim3(TOK / 128, 8 * KSPLIT, NEXP), 256, GM_SMEM>>>(w2h, out);
}